// round 6
// baseline (speedup 1.0000x reference)
#include <cuda_runtime.h>
#include <math.h>

// LineFinderLoss, S = 4096 (square). Output tuple packed: d_out[0] = loss,
// d_out[1 + i*S + j] = cost[i][j].
//
// cost[i][j] = 0.5*((in[i,0]-tg[j,0])^2 + (in[i,1]-tg[j,1])^2)
// loss = ALPHA*sum((in-tg)^2) - S*sum_n log(in[n,4]) + sum_ij (in[j,3]-tg[i,j])^2 / S^2
//
// Key BW insight: the 64 MB cost output fits in the 126 MB L2. Default
// (evict-normal) stores keep it L2-resident across graph replays, so writes
// re-dirty resident lines instead of generating DRAM writebacks; __ldcs on
// the 128 MB read streams keeps them evict-first so they don't displace it.

#define MAXS    4096
#define ALPHA   0.01
#define RTILE   4        // rows per tile
#define CSLICES 4        // column slices (S / (256 threads * 4 floats))
#define GRID    1184     // 148 SMs * 8 resident blocks

// ---------------- device scratch (no allocations allowed) ----------------
// Shifted packed columns: g_t0s[k] = target[k-1, 0]  (k = 1..S), g_t0s[0] junk.
__device__ float  g_t0s[MAXS + 4];
__device__ float  g_t1s[MAXS + 4];
__device__ float  g_ic3[MAXS + 4];       // input[:,3] (unshifted)
__device__ float  g_a0[MAXS];            // input[:,0]  (row scalars)
__device__ float  g_a1[MAXS];            // input[:,1]
__device__ double g_lgpart[MAXS / 256];  // per-pack-block partial of sum log(in[:,4])
__device__ double g_sum_sq;
__device__ double g_sum_t3;
__device__ unsigned int g_ticket;        // dynamic tile counter
__device__ unsigned int g_count;         // completion counter

// ---------------- kernel 1: reset state + gather columns + partial log-sum --
// Runs strictly before main_kernel on the same stream every replay; all replay
// state resets live here, ordered by the kernel boundary.
__global__ void pack_kernel(const float* __restrict__ inp,
                            const float* __restrict__ tgt, int S) {
    if (blockIdx.x == 0 && threadIdx.x == 0) {
        g_ticket = 0u;
        g_count  = 0u;
        g_sum_sq = 0.0;
        g_sum_t3 = 0.0;
    }
    int r = blockIdx.x * blockDim.x + threadIdx.x;
    float lg = 0.0f;
    if (r < S) {
        size_t base = (size_t)r * S;
        g_t0s[r + 1] = tgt[base + 0];
        g_t1s[r + 1] = tgt[base + 1];
        g_a0[r]      = inp[base + 0];
        g_a1[r]      = inp[base + 1];
        g_ic3[r]     = inp[base + 3];
        lg = logf(inp[base + 4]);
        if (r == 0) { g_t0s[0] = 0.0f; g_t1s[0] = 0.0f; }
    }
    #pragma unroll
    for (int off = 16; off > 0; off >>= 1)
        lg += __shfl_down_sync(0xffffffffu, lg, off);
    __shared__ float ws[8];
    int lane = threadIdx.x & 31, wid = threadIdx.x >> 5;
    if (lane == 0) ws[wid] = lg;
    __syncthreads();
    if (threadIdx.x == 0) {
        float s = 0.0f;
        #pragma unroll
        for (int w = 0; w < 8; w++) s += ws[w];
        g_lgpart[blockIdx.x] = (double)s;
    }
}

// ---------------- kernel 2: persistent, dynamically-balanced stream pass ---
// 1184 resident blocks pop 4-row x 1024-col tiles from a global ticket
// (hard-bounded loop: terminates even on corrupt state). Cost stores: thread
// j4 writes cols [4*j4-1 .. 4*j4+2] as an aligned float4 at
// (out + row*S + 4*j4) since out[0] is the loss scalar; pre-shifted t0s/t1s
// keep the matching loads aligned. Stores are DEFAULT policy (evict-normal)
// so the output stays L2-resident across replays; reads are __ldcs.
__global__ __launch_bounds__(256, 8)
void main_kernel(const float* __restrict__ inp,
                 const float* __restrict__ tgt,
                 float* __restrict__ out, int S) {
    const int tid    = threadIdx.x;
    const int lastj4 = (S >> 2) - 1;
    const int ntiles = CSLICES * (S / RTILE);

    __shared__ unsigned int sh_t;
    float acc_sq0 = 0.0f, acc_sq1 = 0.0f;
    float acc_t30 = 0.0f, acc_t31 = 0.0f;

    for (int safety = 0; safety < ntiles + 2; safety++) {
        if (tid == 0) sh_t = atomicAdd(&g_ticket, 1u);
        __syncthreads();
        const unsigned int t = sh_t;
        __syncthreads();
        if (t >= (unsigned int)ntiles) break;

        const int cs   = (int)(t & (CSLICES - 1));
        const int row0 = (int)(t >> 2) * RTILE;
        const int j4   = cs * 256 + tid;
        const bool isFirst = (j4 == 0);
        const bool isLast  = (j4 == lastj4);

        // column-resident data (L1/L2 hits), reused across RTILE rows
        const float4 t0s = ((const float4*)g_t0s)[j4];  // t0[4j-1..4j+2]
        const float4 t1s = ((const float4*)g_t1s)[j4];
        const float4 c3  = ((const float4*)g_ic3)[j4];  // in[4j..4j+3, 3]

        #pragma unroll
        for (int r = 0; r < RTILE; r++) {
            const int row = row0 + r;
            const size_t base = (size_t)row * S;
            const float4 in = __ldcs((const float4*)(inp + base) + j4);
            const float4 tg = __ldcs((const float4*)(tgt + base) + j4);
            const float a0 = g_a0[row];   // broadcast
            const float a1 = g_a1[row];

            float* accq = (r & 1) ? &acc_sq1 : &acc_sq0;
            float* acct = (r & 1) ? &acc_t31 : &acc_t30;
            float d, e;
            d = in.x - tg.x; *accq = fmaf(d, d, *accq);
            e = c3.x - tg.x; *acct = fmaf(e, e, *acct);
            d = in.y - tg.y; *accq = fmaf(d, d, *accq);
            e = c3.y - tg.y; *acct = fmaf(e, e, *acct);
            d = in.z - tg.z; *accq = fmaf(d, d, *accq);
            e = c3.z - tg.z; *acct = fmaf(e, e, *acct);
            d = in.w - tg.w; *accq = fmaf(d, d, *accq);
            e = c3.w - tg.w; *acct = fmaf(e, e, *acct);

            float4 cv;
            float u, v;
            u = a0 - t0s.x; v = a1 - t1s.x; cv.x = 0.5f * fmaf(u, u, v * v);
            u = a0 - t0s.y; v = a1 - t1s.y; cv.y = 0.5f * fmaf(u, u, v * v);
            u = a0 - t0s.z; v = a1 - t1s.z; cv.z = 0.5f * fmaf(u, u, v * v);
            u = a0 - t0s.w; v = a1 - t1s.w; cv.w = 0.5f * fmaf(u, u, v * v);

            if (!isFirst) {
                // out + base + 4*j4 == cost + base + (4*j4 - 1), 16B aligned.
                // DEFAULT store policy: keep line L2-resident across replays.
                ((float4*)(out + base))[j4] = cv;
            } else {
                float* crow = out + 1 + base;   // cost row start (cols 0..2)
                crow[0] = cv.y; crow[1] = cv.z; crow[2] = cv.w;
            }
            if (isLast) {
                u = a0 - g_t0s[S]; v = a1 - g_t1s[S];
                out[1 + base + (size_t)(S - 1)] = 0.5f * fmaf(u, u, v * v);
            }
        }
    }

    float acc_sq = acc_sq0 + acc_sq1;
    float acc_t3 = acc_t30 + acc_t31;

    // block reduce (after all tiles)
    #pragma unroll
    for (int off = 16; off > 0; off >>= 1) {
        acc_sq += __shfl_down_sync(0xffffffffu, acc_sq, off);
        acc_t3 += __shfl_down_sync(0xffffffffu, acc_t3, off);
    }
    __shared__ float s_sq[8], s_t3[8];
    int lane = threadIdx.x & 31, wid = threadIdx.x >> 5;
    if (lane == 0) { s_sq[wid] = acc_sq; s_t3[wid] = acc_t3; }
    __syncthreads();

    __shared__ bool amLast;
    if (threadIdx.x == 0) {
        float r1 = 0.0f, r2 = 0.0f;
        #pragma unroll
        for (int w = 0; w < 8; w++) { r1 += s_sq[w]; r2 += s_t3[w]; }
        atomicAdd(&g_sum_sq, (double)r1);
        atomicAdd(&g_sum_t3, (double)r2);
        __threadfence();
        unsigned int ticket = atomicAdd(&g_count, 1u);
        amLast = (ticket == (unsigned int)gridDim.x - 1u);
    }
    __syncthreads();

    // finishing block computes the loss scalar. NO state mutation here —
    // all resets happen in pack_kernel of the next replay.
    if (amLast && threadIdx.x == 0) {
        double sumsq  = *((volatile double*)&g_sum_sq);
        double sum3   = *((volatile double*)&g_sum_t3);
        double sumlog = 0.0;
        int nlg = S / 256;
        for (int w = 0; w < nlg; w++) sumlog += g_lgpart[w];
        double Sd = (double)S;
        out[0] = (float)(ALPHA * sumsq - Sd * sumlog + sum3 / (Sd * Sd));
    }
}

// ---------------- launch ----------------
extern "C" void kernel_launch(void* const* d_in, const int* in_sizes, int n_in,
                              void* d_out, int out_size) {
    const float* inp = (const float*)d_in[0];
    const float* tgt = (const float*)d_in[1];
    float* out = (float*)d_out;

    long long n = in_sizes[0];
    int S = 1;
    while ((long long)(S + 1) * (S + 1) <= n) S++;   // integer sqrt (S = 4096)
    if (S > MAXS) S = MAXS;

    pack_kernel<<<S / 256, 256>>>(inp, tgt, S);
    main_kernel<<<GRID, 256>>>(inp, tgt, out, S);
}